// round 9
// baseline (speedup 1.0000x reference)
#include <cuda_runtime.h>
#include <cuda_bf16.h>

#define B_ 64
#define T_ 1024
#define I_ 8
#define H_ 512
#define O_ 2
#define NOISE_STD_ 0.05f
#define ALPHA_ 0.2f

#define NT_   128           // 4 warps, one batch per CTA
#define UPT_  4             // hidden units per thread
#define NW_   4

#define SA_   131072.0f     // 2^17 fixed-point scale for recurrence dots (R4 exact)
#define SO_   2097152.0f    // 2^21 fixed-point scale for output dots

// Single-MUFU tanh (~6e-4 rel err; net kernel rel_err ~1e-5, traj-dominated).
__device__ __forceinline__ float tanh_mufu(float x) {
    float r; asm("tanh.approx.f32 %0, %1;" : "=f"(r) : "f"(x)); return r;
}

// Warp-wide integer add-reduction (s32 redux supported on sm_103).
__device__ __forceinline__ int redux_add_s32(int v) {
    int r; asm("redux.sync.add.s32 %0, %1, 0xffffffff;" : "=r"(r) : "r"(v)); return r;
}

// 128-bit volatile smem accesses (single STS.128/LDS.128 => tag travels
// atomically with the data; no barrier/fence needed within the CTA).
__device__ __forceinline__ void stv4(int4* p, int x, int y, int z, int w) {
    asm volatile("st.volatile.v4.b32 [%0], {%1,%2,%3,%4};"
                 :: "l"(p), "r"(x), "r"(y), "r"(z), "r"(w) : "memory");
}
__device__ __forceinline__ int4 ldv4(const int4* p) {
    int4 v;
    asm volatile("ld.volatile.v4.b32 {%0,%1,%2,%3}, [%4];"
                 : "=r"(v.x), "=r"(v.y), "=r"(v.z), "=r"(v.w) : "l"(p) : "memory");
    return v;
}

__global__ __launch_bounds__(NT_, 1)
void lowrank_rnn_kernel(const float* __restrict__ input,   // (B,T,I)
                        const float* __restrict__ noise,   // (B,T,H)
                        const float* __restrict__ wi,      // (I,H)
                        const float* __restrict__ si,      // (I,)
                        const float* __restrict__ m,       // (H,R)
                        const float* __restrict__ n,       // (H,R)
                        const float* __restrict__ wo,      // (H,O)
                        const float* __restrict__ so,      // (O,)
                        const float* __restrict__ h0,      // (H,)
                        float* __restrict__ out,           // (B,T,O)
                        float* __restrict__ traj)          // (B,T,H)
{
    __shared__ int4 s_a[4][NW_];   // (ia0, ia1, io0, tag) tagged ring, 4 slots
    __shared__ int4 s_o[4][NW_];   // (io1, 0,   0,   tag) tagged ring
    __shared__ int4 s_pro[NW_];    // prologue exchange (barrier-ordered)

    const int b    = blockIdx.x;
    const int tid  = threadIdx.x;
    const int warp = tid >> 5;
    const int lane = tid & 31;
    const int k0   = tid * UPT_;

    // ---- per-thread weights (folded constants, identical to R4/R8) ----
    float wif[I_][UPT_];
    #pragma unroll
    for (int i = 0; i < I_; ++i) {
        const float4 w = *(const float4*)(wi + i * H_ + k0);
        const float  s = si[i];
        wif[i][0] = w.x * s; wif[i][1] = w.y * s;
        wif[i][2] = w.z * s; wif[i][3] = w.w * s;
    }
    const float cm  = (ALPHA_ / (float)H_) / SA_;
    const float so0 = (so[0] / (float)H_) * SO_;
    const float so1 = (so[1] / (float)H_) * SO_;
    float m0f[UPT_], m1f[UPT_], n0f[UPT_], n1f[UPT_], wo0f[UPT_], wo1f[UPT_];
    #pragma unroll
    for (int j = 0; j < UPT_; ++j) {
        const int k = k0 + j;
        m0f[j]  = m[k * 2 + 0] * cm;        m1f[j]  = m[k * 2 + 1] * cm;
        n0f[j]  = n[k * 2 + 0] * SA_;       n1f[j]  = n[k * 2 + 1] * SA_;
        wo0f[j] = wo[k * 2 + 0] * so0;      wo1f[j] = wo[k * 2 + 1] * so1;
    }

    float h[UPT_];
    {
        const float4 hh = *(const float4*)(h0 + k0);
        h[0] = hh.x; h[1] = hh.y; h[2] = hh.z; h[3] = hh.w;
    }

    const float* nz_base   = noise + (size_t)b * T_ * H_ + k0;
    const float* in_base   = input + (size_t)b * T_ * I_;
    float*       traj_base = traj  + (size_t)b * T_ * H_ + k0;
    float*       out_base  = out   + (size_t)b * T_ * O_;

    // ---- prefetch rings, depth 4: noise (per-thread) + input row (broadcast) ----
    float4 ring[4];
    float4 ir0[4], ir1[4];
    #pragma unroll
    for (int j = 0; j < 4; ++j) {
        ring[j] = *(const float4*)(nz_base + (size_t)j * H_);
        ir0[j]  = *(const float4*)(in_base + j * I_);
        ir1[j]  = *(const float4*)(in_base + j * I_ + 4);
    }

    // ---- init ring tags to -1 (graph replay leaves stale smem), then prologue ----
    if (lane == 0) {
        #pragma unroll
        for (int s = 0; s < 4; ++s) {
            stv4(&s_a[s][warp], 0, 0, 0, -1);
            stv4(&s_o[s][warp], 0, 0, 0, -1);
        }
    }

    // ---- prologue: a = n^T r_0 via one barrier-ordered exchange ----
    float a0, a1;
    {
        float pa0 = 0.0f, pa1 = 0.0f;
        #pragma unroll
        for (int u = 0; u < UPT_; ++u) {
            const float r = tanh_mufu(h[u]);
            pa0 = fmaf(r, n0f[u], pa0);
            pa1 = fmaf(r, n1f[u], pa1);
        }
        const int ia0 = redux_add_s32(__float2int_rn(pa0));
        const int ia1 = redux_add_s32(__float2int_rn(pa1));
        if (lane == 0) s_pro[warp] = make_int4(ia0, ia1, 0, 0);
        __syncthreads();       // orders tag-init and prologue partials
        int sx = 0, sy = 0;
        #pragma unroll
        for (int w = 0; w < NW_; ++w) {
            const int4 v = s_pro[w];
            sx += v.x; sy += v.y;
        }
        a0 = (float)sx; a1 = (float)sy;
    }

    // ---- main scan: barrier-free, tag-polled exchange ----
    #pragma unroll 4
    for (int t = 0; t < T_; ++t) {
        const int j = t & 3;
        const float4 nz = ring[j];
        const float4 i0 = ir0[j];
        const float4 i1 = ir1[j];
        int tp = t + 4; if (tp > T_ - 1) tp = T_ - 1;
        ring[j] = *(const float4*)(nz_base + (size_t)tp * H_);
        ir0[j]  = *(const float4*)(in_base + tp * I_);
        ir1[j]  = *(const float4*)(in_base + tp * I_ + 4);

        // input projection p_t (off critical path)
        float p[UPT_];
        #pragma unroll
        for (int u = 0; u < UPT_; ++u) {
            float pp = i0.x * wif[0][u];
            pp = fmaf(i0.y, wif[1][u], pp);
            pp = fmaf(i0.z, wif[2][u], pp);
            pp = fmaf(i0.w, wif[3][u], pp);
            pp = fmaf(i1.x, wif[4][u], pp);
            pp = fmaf(i1.y, wif[5][u], pp);
            pp = fmaf(i1.z, wif[6][u], pp);
            pp = fmaf(i1.w, wif[7][u], pp);
            p[u] = pp;
        }
        const float nza[UPT_] = {nz.x, nz.y, nz.z, nz.w};

        // h' = 0.8h + 0.05nz + 0.2p + a0*m0f + a1*m1f ; r' = tanh(h')
        float pa0 = 0.0f, pa1 = 0.0f, po0 = 0.0f, po1 = 0.0f;
        #pragma unroll
        for (int u = 0; u < UPT_; ++u) {
            const float base = fmaf(NOISE_STD_, nza[u], ALPHA_ * p[u]);
            const float hb   = fmaf(1.0f - ALPHA_, h[u], base);
            float hx = fmaf(a0, m0f[u], hb);
            hx       = fmaf(a1, m1f[u], hx);
            h[u] = hx;
            const float r = tanh_mufu(hx);
            pa0 = fmaf(r, n0f[u], pa0);
            pa1 = fmaf(r, n1f[u], pa1);
            po0 = fmaf(r, wo0f[u], po0);
            po1 = fmaf(r, wo1f[u], po1);
        }

        // traj[t] = h_{t+1}, coalesced STG.128
        *(float4*)(traj_base + (size_t)t * H_) = make_float4(h[0], h[1], h[2], h[3]);

        // fixed-point warp reduction (a-pair first: on critical path)
        const int ia0 = redux_add_s32(__float2int_rn(pa0));
        const int ia1 = redux_add_s32(__float2int_rn(pa1));
        const int io0 = redux_add_s32(__float2int_rn(po0));
        const int io1 = redux_add_s32(__float2int_rn(po1));

        // publish: single STS.128 carries data + tag atomically
        if (lane == 0) {
            stv4(&s_a[j][warp], ia0, ia1, io0, t);
            stv4(&s_o[j][warp], io1, 0, 0, t);
        }

        // consume: spin until all 4 warp slots carry tag == t (no barrier)
        int4 v0, v1, v2, v3;
        do {
            v0 = ldv4(&s_a[j][0]);
            v1 = ldv4(&s_a[j][1]);
            v2 = ldv4(&s_a[j][2]);
            v3 = ldv4(&s_a[j][3]);
        } while (((v0.w ^ t) | (v1.w ^ t) | (v2.w ^ t) | (v3.w ^ t)) != 0);

        a0 = (float)((v0.x + v1.x) + (v2.x + v3.x));
        a1 = (float)((v0.y + v1.y) + (v2.y + v3.y));

        // out[t]: single thread, off the critical path of other warps
        if (tid == 0) {
            int4 u0, u1, u2, u3;
            do {
                u0 = ldv4(&s_o[j][0]);
                u1 = ldv4(&s_o[j][1]);
                u2 = ldv4(&s_o[j][2]);
                u3 = ldv4(&s_o[j][3]);
            } while (((u0.w ^ t) | (u1.w ^ t) | (u2.w ^ t) | (u3.w ^ t)) != 0);
            const float o0 = (float)((v0.z + v1.z) + (v2.z + v3.z)) * (1.0f / SO_);
            const float o1 = (float)((u0.x + u1.x) + (u2.x + u3.x)) * (1.0f / SO_);
            *(float2*)(out_base + (size_t)t * O_) = make_float2(o0, o1);
        }
    }
}

extern "C" void kernel_launch(void* const* d_in, const int* in_sizes, int n_in,
                              void* d_out, int out_size) {
    const float* input = (const float*)d_in[0];
    const float* noise = (const float*)d_in[1];
    const float* wi    = (const float*)d_in[2];
    const float* si    = (const float*)d_in[3];
    const float* m     = (const float*)d_in[4];
    const float* n     = (const float*)d_in[5];
    const float* wo    = (const float*)d_in[6];
    const float* so    = (const float*)d_in[7];
    const float* h0    = (const float*)d_in[8];

    float* out  = (float*)d_out;                         // (B,T,O) first
    float* traj = (float*)d_out + (size_t)B_ * T_ * O_;  // then (B,T,H)

    lowrank_rnn_kernel<<<B_, NT_>>>(input, noise, wi, si, m, n, wo, so, h0,
                                    out, traj);
}